// round 8
// baseline (speedup 1.0000x reference)
#include <cuda_runtime.h>
#include <cuda_bf16.h>
#include <cuda_fp16.h>
#include <cstdint>

#define MAX_N 100000
#define MAX_E 1600000
#define HID   64
#define SCAN_TILE 1024
#define MAX_BLKS  ((MAX_N + SCAN_TILE - 1) / SCAN_TILE)

// Scratch: __device__ globals, referenced directly by symbol in device code.
__device__ __align__(16) float   g_bufA[MAX_N * HID];
__device__ __align__(16) float   g_bufB[MAX_N * HID];
__device__ __align__(16) __half2 g_h16[MAX_N * 32];   // fp16 copy of gemm output (gather feed)
__device__ float g_dis[MAX_N];
__device__ int   g_hist[MAX_N];      // edge in-degree (no self-loop)
__device__ int   g_rowptr[MAX_N];
__device__ int   g_cursor[MAX_N];
__device__ int   g_uhist[MAX_N];     // user_idx counts
__device__ int   g_urowptr[MAX_N];
__device__ int   g_ucursor[MAX_N];
__device__ int   g_unodes[MAX_N];    // CSR payload for user_idx
__device__ int   g_bsums[2 * MAX_BLKS + 2];
__device__ __align__(8) int2 g_erec[MAX_E];  // {src, norm bits}

// ---- packed f32x2 helpers (ptxas never auto-fuses these) ------------------
__device__ __forceinline__ unsigned long long ffma2(unsigned long long a,
                                                    unsigned long long b,
                                                    unsigned long long c) {
    unsigned long long d;
    asm("fma.rn.f32x2 %0, %1, %2, %3;" : "=l"(d) : "l"(a), "l"(b), "l"(c));
    return d;
}
__device__ __forceinline__ void unpack2(unsigned long long v, float& lo, float& hi) {
    asm("mov.b64 {%0, %1}, %2;" : "=f"(lo), "=f"(hi) : "l"(v));
}

// ---------------------------------------------------------------------------
__global__ void k_zero_graph(int N) {
    int i = blockIdx.x * blockDim.x + threadIdx.x;
    if (i < N) { g_hist[i] = 0; g_cursor[i] = 0; g_uhist[i] = 0; g_ucursor[i] = 0; }
}

__global__ void k_histboth(const int* __restrict__ dst, const int* __restrict__ uidx,
                           int E, int N) {
    int i = blockIdx.x * blockDim.x + threadIdx.x;
    if (i < E)          atomicAdd(&g_hist[dst[i]], 1);
    else if (i < E + N) atomicAdd(&g_uhist[uidx[i - E]], 1);
}

// fused hierarchical scan, both CSRs in one grid; dis folded into which==0 pass
__global__ void __launch_bounds__(SCAN_TILE) k_scan_local(int nblk, int N) {
    __shared__ int sh[SCAN_TILE];
    int which = (blockIdx.x >= nblk) ? 1 : 0;
    int blk = blockIdx.x - which * nblk;
    const int* in = which ? g_uhist : g_hist;
    int* outp     = which ? g_urowptr : g_rowptr;
    int tid = threadIdx.x;
    int i = blk * SCAN_TILE + tid;
    int v = (i < N) ? in[i] : 0;
    sh[tid] = v;
    __syncthreads();
    for (int off = 1; off < SCAN_TILE; off <<= 1) {
        int t = (tid >= off) ? sh[tid - off] : 0;
        __syncthreads();
        sh[tid] += t;
        __syncthreads();
    }
    if (i < N) {
        outp[i] = sh[tid] - v;
        if (!which) g_dis[i] = rsqrtf((float)(v + 1));   // deg+1 (self-loop)
    }
    if (tid == SCAN_TILE - 1) g_bsums[blockIdx.x] = sh[tid];
}

__global__ void k_scan_sums(int nblk) {
    int t = threadIdx.x;
    if (t < 2) {
        int acc = 0;
        for (int b = t * nblk; b < (t + 1) * nblk; ++b) {
            int v = g_bsums[b]; g_bsums[b] = acc; acc += v;
        }
    }
}

__global__ void __launch_bounds__(SCAN_TILE) k_scan_add(int nblk, int N) {
    int which = (blockIdx.x >= nblk) ? 1 : 0;
    int blk = blockIdx.x - which * nblk;
    int* outp = which ? g_urowptr : g_rowptr;
    int i = blk * SCAN_TILE + threadIdx.x;
    if (i < N) outp[i] += g_bsums[blockIdx.x];
}

__global__ void k_scatterboth(const int* __restrict__ src, const int* __restrict__ dst,
                              const int* __restrict__ uidx, int E, int N) {
    int i = blockIdx.x * blockDim.x + threadIdx.x;
    if (i < E) {
        int s = src[i];
        int d = dst[i];
        int pos = g_rowptr[d] + atomicAdd(&g_cursor[d], 1);
        g_erec[pos] = make_int2(s, __float_as_int(g_dis[s] * g_dis[d]));
    } else if (i < E + N) {
        int n = i - E;
        int u = uidx[n];
        int pos = g_urowptr[u] + atomicAdd(&g_ucursor[u], 1);
        g_unodes[pos] = n;
    }
}

// ---------------------------------------------------------------------------
// Gather aggregation: warp per dst node, lane owns cols {2*lane, 2*lane+1}.
// Neighbor gather from fp16 (g_h16, written by gemm epilogue); self term,
// accumulation, bias and output stay fp32. Writes g_bufB.
// ---------------------------------------------------------------------------
__global__ void __launch_bounds__(256) k_aggr(const float* __restrict__ bias,
                                              int N, int do_relu) {
    int d = (blockIdx.x * blockDim.x + threadIdx.x) >> 5;
    int lane = threadIdx.x & 31;
    if (d >= N) return;

    const float2*  __restrict__ h2 = (const float2*)g_bufA;
    const __half2* __restrict__ hh = (const __half2*)g_h16;

    float sd = g_dis[d];
    float w = sd * sd;
    float2 hv = h2[(size_t)d * 32 + lane];
    float ax = w * hv.x;
    float ay = w * hv.y;

    int beg = g_rowptr[d];
    int deg = g_hist[d];
    for (int base = 0; base < deg; base += 32) {
        int n = deg - base; if (n > 32) n = 32;
        int2 r = g_erec[beg + base + ((lane < n) ? lane : 0)];
#pragma unroll 4
        for (int j = 0; j < n; ++j) {
            int   s    = __shfl_sync(0xffffffffu, r.x, j);
            float norm = __int_as_float(__shfl_sync(0xffffffffu, r.y, j));
            float2 hs = __half22float2(hh[(size_t)s * 32 + lane]);
            ax = fmaf(norm, hs.x, ax);
            ay = fmaf(norm, hs.y, ay);
        }
    }

    float2 bb = ((const float2*)bias)[lane];
    ax += bb.x; ay += bb.y;
    if (do_relu) { ax = fmaxf(ax, 0.f); ay = fmaxf(ay, 0.f); }
    ((float2*)g_bufB)[(size_t)d * 32 + lane] = make_float2(ax, ay);
}

// ---------------------------------------------------------------------------
// scatter-mean as gather: warp per user u; float2 lanes; plain store to d_out.
// ---------------------------------------------------------------------------
__global__ void __launch_bounds__(256) k_umean(float* __restrict__ out, int N) {
    int u = (blockIdx.x * blockDim.x + threadIdx.x) >> 5;
    int lane = threadIdx.x & 31;
    if (u >= N) return;
    const float2* __restrict__ h2 = (const float2*)g_bufB;
    int cnt = g_uhist[u];
    float ax = 0.f, ay = 0.f;
    int beg = g_urowptr[u];
    for (int base = 0; base < cnt; base += 32) {
        int n = cnt - base; if (n > 32) n = 32;
        int node_l = g_unodes[beg + base + ((lane < n) ? lane : 0)];
#pragma unroll 4
        for (int j = 0; j < n; ++j) {
            int node = __shfl_sync(0xffffffffu, node_l, j);
            float2 hs = h2[(size_t)node * 32 + lane];
            ax += hs.x; ay += hs.y;
        }
    }
    float inv = (cnt > 0) ? 1.0f / (float)cnt : 0.f;
    ((float2*)out)[(size_t)u * 32 + lane] = make_float2(ax * inv, ay * inv);
}

// ---------------------------------------------------------------------------
// GEMM via packed FFMA2: bufA[N][64] (+ fp16 copy) = A[N][K] @ W[K][64].
// 128x64 block tile, 256 threads, 4 row-pair x 4 col f32x2 accumulators.
// W chunk pre-duplicated as {w,w} pairs in smem (no per-k packing); A chunk
// staged k-major so a row pair is one half of an LDS.128.
// ---------------------------------------------------------------------------
template <int K>
__global__ void __launch_bounds__(256) gemm_kernel(const float* __restrict__ Ax,
                                                   const float* __restrict__ W,
                                                   int in_sel, int N) {
    const float* __restrict__ A = in_sel ? (const float*)g_bufB : Ax;
    __shared__ __align__(16) float2 Wp[32][64];   // dup-packed W chunk (16 KB)
    __shared__ __align__(16) float  xs[32][136];  // k-major A chunk (17.4 KB)

    int tid = threadIdx.x;
    int row0 = blockIdx.x * 128;
    int tx = tid & 15;                  // col group: 4 cols
    int ty = tid >> 4;                  // row group: 8 rows (4 pairs)

    unsigned long long acc[4][4];       // [row pair][col]
#pragma unroll
    for (int i = 0; i < 4; ++i)
#pragma unroll
        for (int j = 0; j < 4; ++j) acc[i][j] = 0ULL;

    for (int k0 = 0; k0 < K; k0 += 32) {
        __syncthreads();
        // stage dup-packed W chunk: 32x64 entries, 8 per thread
#pragma unroll
        for (int i = tid; i < 32 * 64; i += 256) {
            int kk = i >> 6, c = i & 63;
            float wv = W[(k0 + kk) * 64 + c];
            Wp[kk][c] = make_float2(wv, wv);
        }
        // stage A chunk k-major
#pragma unroll
        for (int it = 0; it < 4; ++it) {
            int r  = (tid >> 3) + it * 32;   // 0..127
            int kk = (tid & 7) * 4;          // 0..28
            int row = row0 + r;
            float4 v = make_float4(0.f, 0.f, 0.f, 0.f);
            if (row < N)
                v = *(const float4*)(A + (size_t)row * K + k0 + kk);
            xs[kk + 0][r] = v.x; xs[kk + 1][r] = v.y;
            xs[kk + 2][r] = v.z; xs[kk + 3][r] = v.w;
        }
        __syncthreads();
#pragma unroll
        for (int k = 0; k < 32; ++k) {
            ulonglong2 w01 = *(const ulonglong2*)&Wp[k][tx * 4];
            ulonglong2 w23 = *(const ulonglong2*)&Wp[k][tx * 4 + 2];
            ulonglong2 a01 = *(const ulonglong2*)&xs[k][ty * 8];
            ulonglong2 a23 = *(const ulonglong2*)&xs[k][ty * 8 + 4];
            unsigned long long ap[4] = {a01.x, a01.y, a23.x, a23.y};
            unsigned long long wd[4] = {w01.x, w01.y, w23.x, w23.y};
#pragma unroll
            for (int i = 0; i < 4; ++i) {
                acc[i][0] = ffma2(ap[i], wd[0], acc[i][0]);
                acc[i][1] = ffma2(ap[i], wd[1], acc[i][1]);
                acc[i][2] = ffma2(ap[i], wd[2], acc[i][2]);
                acc[i][3] = ffma2(ap[i], wd[3], acc[i][3]);
            }
        }
    }
#pragma unroll
    for (int i = 0; i < 4; ++i) {
        float lo0, hi0, lo1, hi1, lo2, hi2, lo3, hi3;
        unpack2(acc[i][0], lo0, hi0);
        unpack2(acc[i][1], lo1, hi1);
        unpack2(acc[i][2], lo2, hi2);
        unpack2(acc[i][3], lo3, hi3);
        int rowA = row0 + ty * 8 + 2 * i;
        int rowB = rowA + 1;
        if (rowA < N) {
            *(float4*)(&g_bufA[(size_t)rowA * 64 + tx * 4]) =
                make_float4(lo0, lo1, lo2, lo3);
            g_h16[(size_t)rowA * 32 + tx * 2 + 0] = __floats2half2_rn(lo0, lo1);
            g_h16[(size_t)rowA * 32 + tx * 2 + 1] = __floats2half2_rn(lo2, lo3);
        }
        if (rowB < N) {
            *(float4*)(&g_bufA[(size_t)rowB * 64 + tx * 4]) =
                make_float4(hi0, hi1, hi2, hi3);
            g_h16[(size_t)rowB * 32 + tx * 2 + 0] = __floats2half2_rn(hi0, hi1);
            g_h16[(size_t)rowB * 32 + tx * 2 + 1] = __floats2half2_rn(hi2, hi3);
        }
    }
}

// ---------------------------------------------------------------------------
static inline int cdiv(int a, int b) { return (a + b - 1) / b; }

extern "C" void kernel_launch(void* const* d_in, const int* in_sizes, int n_in,
                              void* d_out, int out_size) {
    const float* x    = (const float*)d_in[0];
    const int*   ei   = (const int*)d_in[1];      // int32 per harness dtype contract
    const int*   uidx = (const int*)d_in[2];
    const float* W1   = (const float*)d_in[3];
    const float* b1   = (const float*)d_in[4];
    const float* W2   = (const float*)d_in[5];
    const float* b2   = (const float*)d_in[6];
    float* out = (float*)d_out;

    const int N = in_sizes[2];
    const int E = in_sizes[1] / 2;
    const int* src = ei;
    const int* dst = ei + E;

    const int TB = 256;
    const int nblk = cdiv(N, SCAN_TILE);

    // 1-3: graph prep
    k_zero_graph<<<cdiv(N, TB), TB>>>(N);
    k_histboth<<<cdiv(E + N, TB), TB>>>(dst, uidx, E, N);
    k_scan_local<<<2 * nblk, SCAN_TILE>>>(nblk, N);
    // 4: gemm1 (x -> bufA + h16) — kept at slot 4 for the ncu window
    gemm_kernel<128><<<cdiv(N, 128), 256>>>(x, W1, 0, N);
    // 5-7: finish CSRs
    k_scan_sums<<<1, 32>>>(nblk);
    k_scan_add<<<2 * nblk, SCAN_TILE>>>(nblk, N);
    k_scatterboth<<<cdiv(E + N, TB), TB>>>(src, dst, uidx, E, N);
    // 8: layer-1 aggregate (bufA/h16 -> bufB, +b1, relu)
    k_aggr<<<cdiv(N * 32, TB), TB>>>(b1, N, 1);
    // 9-10: layer 2
    gemm_kernel<64><<<cdiv(N, 128), 256>>>(x, W2, 1, N);   // bufB -> bufA + h16
    k_aggr<<<cdiv(N * 32, TB), TB>>>(b2, N, 0);            // bufA/h16 -> bufB
    // 11: scatter-mean (bufB -> out)
    k_umean<<<cdiv(N * 32, TB), TB>>>(out, N);
}

// round 9
// speedup vs baseline: 1.2562x; 1.2562x over previous
#include <cuda_runtime.h>
#include <cuda_bf16.h>
#include <cstdint>

#define MAX_N 100000
#define MAX_E 1600000
#define HID   64
#define SCAN_TILE 1024
#define MAX_BLKS  ((MAX_N + SCAN_TILE - 1) / SCAN_TILE)

// Scratch: __device__ globals, referenced directly by symbol in device code.
__device__ __align__(16) float g_bufA[MAX_N * HID];
__device__ __align__(16) float g_bufB[MAX_N * HID];
__device__ float g_dis[MAX_N];
__device__ int   g_hist[MAX_N];      // edge in-degree (no self-loop)
__device__ int   g_rowptr[MAX_N];
__device__ int   g_cursor[MAX_N];
__device__ int   g_uhist[MAX_N];     // user_idx counts
__device__ int   g_urowptr[MAX_N];
__device__ int   g_ucursor[MAX_N];
__device__ int   g_unodes[MAX_N];    // CSR payload for user_idx
__device__ int   g_bsums[2 * MAX_BLKS + 2];
__device__ __align__(8) int2 g_erec[MAX_E];  // {src, norm bits}

// ---- packed f32x2 helpers (ptxas never auto-fuses these) ------------------
__device__ __forceinline__ unsigned long long ffma2(unsigned long long a,
                                                    unsigned long long b,
                                                    unsigned long long c) {
    unsigned long long d;
    asm("fma.rn.f32x2 %0, %1, %2, %3;" : "=l"(d) : "l"(a), "l"(b), "l"(c));
    return d;
}
__device__ __forceinline__ unsigned long long pack2(float lo, float hi) {
    unsigned long long d;
    asm("mov.b64 %0, {%1, %2};" : "=l"(d) : "f"(lo), "f"(hi));
    return d;
}
__device__ __forceinline__ void unpack2(unsigned long long v, float& lo, float& hi) {
    asm("mov.b64 {%0, %1}, %2;" : "=f"(lo), "=f"(hi) : "l"(v));
}

// ---------------------------------------------------------------------------
__global__ void k_zero_graph(int N) {
    int i = blockIdx.x * blockDim.x + threadIdx.x;
    if (i < N) { g_hist[i] = 0; g_cursor[i] = 0; g_uhist[i] = 0; g_ucursor[i] = 0; }
}

__global__ void k_histboth(const int* __restrict__ dst, const int* __restrict__ uidx,
                           int E, int N) {
    int i = blockIdx.x * blockDim.x + threadIdx.x;
    if (i < E)          atomicAdd(&g_hist[dst[i]], 1);
    else if (i < E + N) atomicAdd(&g_uhist[uidx[i - E]], 1);
}

// fused hierarchical scan, both CSRs in one grid; dis folded into which==0 pass
__global__ void __launch_bounds__(SCAN_TILE) k_scan_local(int nblk, int N) {
    __shared__ int sh[SCAN_TILE];
    int which = (blockIdx.x >= nblk) ? 1 : 0;
    int blk = blockIdx.x - which * nblk;
    const int* in = which ? g_uhist : g_hist;
    int* outp     = which ? g_urowptr : g_rowptr;
    int tid = threadIdx.x;
    int i = blk * SCAN_TILE + tid;
    int v = (i < N) ? in[i] : 0;
    sh[tid] = v;
    __syncthreads();
    for (int off = 1; off < SCAN_TILE; off <<= 1) {
        int t = (tid >= off) ? sh[tid - off] : 0;
        __syncthreads();
        sh[tid] += t;
        __syncthreads();
    }
    if (i < N) {
        outp[i] = sh[tid] - v;
        if (!which) g_dis[i] = rsqrtf((float)(v + 1));   // deg+1 (self-loop)
    }
    if (tid == SCAN_TILE - 1) g_bsums[blockIdx.x] = sh[tid];
}

__global__ void k_scan_sums(int nblk) {
    int t = threadIdx.x;
    if (t < 2) {
        int acc = 0;
        for (int b = t * nblk; b < (t + 1) * nblk; ++b) {
            int v = g_bsums[b]; g_bsums[b] = acc; acc += v;
        }
    }
}

__global__ void __launch_bounds__(SCAN_TILE) k_scan_add(int nblk, int N) {
    int which = (blockIdx.x >= nblk) ? 1 : 0;
    int blk = blockIdx.x - which * nblk;
    int* outp = which ? g_urowptr : g_rowptr;
    int i = blk * SCAN_TILE + threadIdx.x;
    if (i < N) outp[i] += g_bsums[blockIdx.x];
}

__global__ void k_scatterboth(const int* __restrict__ src, const int* __restrict__ dst,
                              const int* __restrict__ uidx, int E, int N) {
    int i = blockIdx.x * blockDim.x + threadIdx.x;
    if (i < E) {
        int s = src[i];
        int d = dst[i];
        int pos = g_rowptr[d] + atomicAdd(&g_cursor[d], 1);
        g_erec[pos] = make_int2(s, __float_as_int(g_dis[s] * g_dis[d]));
    } else if (i < E + N) {
        int n = i - E;
        int u = uidx[n];
        int pos = g_urowptr[u] + atomicAdd(&g_ucursor[u], 1);
        g_unodes[pos] = n;
    }
}

// ---------------------------------------------------------------------------
// Gather aggregation: warp per dst node, lane owns cols {2*lane, 2*lane+1}
// (float2). Edge records read cooperatively (32/warp, coalesced) and
// shuffle-broadcast. Reads g_bufA, writes g_bufB.
// ---------------------------------------------------------------------------
__global__ void __launch_bounds__(256) k_aggr(const float* __restrict__ bias,
                                              int N, int do_relu) {
    int d = (blockIdx.x * blockDim.x + threadIdx.x) >> 5;
    int lane = threadIdx.x & 31;
    if (d >= N) return;

    const float2* __restrict__ h2 = (const float2*)g_bufA;

    float sd = g_dis[d];
    float w = sd * sd;
    float2 hv = h2[(size_t)d * 32 + lane];
    float ax = w * hv.x;
    float ay = w * hv.y;

    int beg = g_rowptr[d];
    int deg = g_hist[d];
    for (int base = 0; base < deg; base += 32) {
        int n = deg - base; if (n > 32) n = 32;
        int2 r = g_erec[beg + base + ((lane < n) ? lane : 0)];
#pragma unroll 4
        for (int j = 0; j < n; ++j) {
            int   s    = __shfl_sync(0xffffffffu, r.x, j);
            float norm = __int_as_float(__shfl_sync(0xffffffffu, r.y, j));
            float2 hs = h2[(size_t)s * 32 + lane];
            ax = fmaf(norm, hs.x, ax);
            ay = fmaf(norm, hs.y, ay);
        }
    }

    float2 bb = ((const float2*)bias)[lane];
    ax += bb.x; ay += bb.y;
    if (do_relu) { ax = fmaxf(ax, 0.f); ay = fmaxf(ay, 0.f); }
    ((float2*)g_bufB)[(size_t)d * 32 + lane] = make_float2(ax, ay);
}

// ---------------------------------------------------------------------------
// scatter-mean as gather: warp per user u; float2 lanes; plain store to d_out.
// ---------------------------------------------------------------------------
__global__ void __launch_bounds__(256) k_umean(float* __restrict__ out, int N) {
    int u = (blockIdx.x * blockDim.x + threadIdx.x) >> 5;
    int lane = threadIdx.x & 31;
    if (u >= N) return;
    const float2* __restrict__ h2 = (const float2*)g_bufB;
    int cnt = g_uhist[u];
    float ax = 0.f, ay = 0.f;
    int beg = g_urowptr[u];
    for (int base = 0; base < cnt; base += 32) {
        int n = cnt - base; if (n > 32) n = 32;
        int node_l = g_unodes[beg + base + ((lane < n) ? lane : 0)];
#pragma unroll 4
        for (int j = 0; j < n; ++j) {
            int node = __shfl_sync(0xffffffffu, node_l, j);
            float2 hs = h2[(size_t)node * 32 + lane];
            ax += hs.x; ay += hs.y;
        }
    }
    float inv = (cnt > 0) ? 1.0f / (float)cnt : 0.f;
    ((float2*)out)[(size_t)u * 32 + lane] = make_float2(ax * inv, ay * inv);
}

// ---------------------------------------------------------------------------
// GEMM via packed FFMA2 (R7-verified form): g_bufA[N][64] = A[N][K] @ W[K][64].
// 128x64 block tile, 256 threads, 4 row-pair x 4 col f32x2 accumulators.
// A staged k-major (row pair = one LDS.64, warp-broadcast); W read as one
// LDS.128 and dup-packed in registers (alu movs are cheaper than extra LDS).
// min 3 CTAs/SM to cover LDS/FFMA latency (regs were 64 at occ 39.6%).
// ---------------------------------------------------------------------------
template <int K>
__global__ void __launch_bounds__(256, 3) gemm_kernel(const float* __restrict__ Ax,
                                                      const float* __restrict__ W,
                                                      int in_sel, int N) {
    const float* __restrict__ A = in_sel ? (const float*)g_bufB : Ax;
    __shared__ float Ws[K][64];                 // 32 KB (K=128) / 16 KB (K=64)
    __shared__ __align__(16) float xs[32][134]; // k-major A chunk, padded

    int tid = threadIdx.x;
    for (int i = tid; i < K * 64; i += 256) Ws[i >> 6][i & 63] = W[i];

    int row0 = blockIdx.x * 128;
    int tx = tid & 15;                  // col group: 4 cols
    int ty = tid >> 4;                  // row group: 8 rows (4 pairs)

    unsigned long long acc[4][4];       // [row pair][col]
#pragma unroll
    for (int i = 0; i < 4; ++i)
#pragma unroll
        for (int j = 0; j < 4; ++j) acc[i][j] = 0ULL;

    for (int k0 = 0; k0 < K; k0 += 32) {
        __syncthreads();
#pragma unroll
        for (int it = 0; it < 4; ++it) {
            int r  = (tid >> 3) + it * 32;   // 0..127
            int kk = (tid & 7) * 4;          // 0..28
            int row = row0 + r;
            float4 v = make_float4(0.f, 0.f, 0.f, 0.f);
            if (row < N)
                v = *(const float4*)(A + (size_t)row * K + k0 + kk);
            xs[kk + 0][r] = v.x; xs[kk + 1][r] = v.y;
            xs[kk + 2][r] = v.z; xs[kk + 3][r] = v.w;
        }
        __syncthreads();
#pragma unroll
        for (int k = 0; k < 32; ++k) {
            float4 wv = *(const float4*)&Ws[k0 + k][tx * 4];
            unsigned long long wd[4];
            wd[0] = pack2(wv.x, wv.x); wd[1] = pack2(wv.y, wv.y);
            wd[2] = pack2(wv.z, wv.z); wd[3] = pack2(wv.w, wv.w);
            unsigned long long ap[4];
#pragma unroll
            for (int i = 0; i < 4; ++i)
                ap[i] = *(const unsigned long long*)&xs[k][ty * 8 + 2 * i];
#pragma unroll
            for (int i = 0; i < 4; ++i) {
                acc[i][0] = ffma2(ap[i], wd[0], acc[i][0]);
                acc[i][1] = ffma2(ap[i], wd[1], acc[i][1]);
                acc[i][2] = ffma2(ap[i], wd[2], acc[i][2]);
                acc[i][3] = ffma2(ap[i], wd[3], acc[i][3]);
            }
        }
    }
#pragma unroll
    for (int i = 0; i < 4; ++i) {
        float lo0, hi0, lo1, hi1, lo2, hi2, lo3, hi3;
        unpack2(acc[i][0], lo0, hi0);
        unpack2(acc[i][1], lo1, hi1);
        unpack2(acc[i][2], lo2, hi2);
        unpack2(acc[i][3], lo3, hi3);
        int rowA = row0 + ty * 8 + 2 * i;
        int rowB = rowA + 1;
        if (rowA < N)
            *(float4*)(&g_bufA[(size_t)rowA * 64 + tx * 4]) =
                make_float4(lo0, lo1, lo2, lo3);
        if (rowB < N)
            *(float4*)(&g_bufA[(size_t)rowB * 64 + tx * 4]) =
                make_float4(hi0, hi1, hi2, hi3);
    }
}

// ---------------------------------------------------------------------------
static inline int cdiv(int a, int b) { return (a + b - 1) / b; }

extern "C" void kernel_launch(void* const* d_in, const int* in_sizes, int n_in,
                              void* d_out, int out_size) {
    const float* x    = (const float*)d_in[0];
    const int*   ei   = (const int*)d_in[1];      // int32 per harness dtype contract
    const int*   uidx = (const int*)d_in[2];
    const float* W1   = (const float*)d_in[3];
    const float* b1   = (const float*)d_in[4];
    const float* W2   = (const float*)d_in[5];
    const float* b2   = (const float*)d_in[6];
    float* out = (float*)d_out;

    const int N = in_sizes[2];
    const int E = in_sizes[1] / 2;
    const int* src = ei;
    const int* dst = ei + E;

    const int TB = 256;
    const int nblk = cdiv(N, SCAN_TILE);

    // 1-3: graph prep
    k_zero_graph<<<cdiv(N, TB), TB>>>(N);
    k_histboth<<<cdiv(E + N, TB), TB>>>(dst, uidx, E, N);
    k_scan_local<<<2 * nblk, SCAN_TILE>>>(nblk, N);
    // 4: gemm1 (x -> bufA) — kept at slot 4 for the ncu window
    gemm_kernel<128><<<cdiv(N, 128), 256>>>(x, W1, 0, N);
    // 5-7: finish CSRs
    k_scan_sums<<<1, 32>>>(nblk);
    k_scan_add<<<2 * nblk, SCAN_TILE>>>(nblk, N);
    k_scatterboth<<<cdiv(E + N, TB), TB>>>(src, dst, uidx, E, N);
    // 8: layer-1 aggregate (bufA -> bufB, +b1, relu)
    k_aggr<<<cdiv(N * 32, TB), TB>>>(b1, N, 1);
    // 9-10: layer 2
    gemm_kernel<64><<<cdiv(N, 128), 256>>>(x, W2, 1, N);   // bufB -> bufA
    k_aggr<<<cdiv(N * 32, TB), TB>>>(b2, N, 0);            // bufA -> bufB
    // 11: scatter-mean (bufB -> out)
    k_umean<<<cdiv(N * 32, TB), TB>>>(out, N);
}

// round 10
// speedup vs baseline: 1.3800x; 1.0985x over previous
#include <cuda_runtime.h>
#include <cuda_bf16.h>
#include <cstdint>

#define MAX_N 100000
#define MAX_E 1600000
#define HID   64
#define SCAN_TILE 1024
#define MAX_BLKS  ((MAX_N + SCAN_TILE - 1) / SCAN_TILE)

// Scratch: __device__ globals, referenced directly by symbol in device code.
__device__ __align__(16) float g_bufA[MAX_N * HID];
__device__ __align__(16) float g_bufB[MAX_N * HID];
__device__ float g_dis[MAX_N];
__device__ int   g_hist[MAX_N];      // edge in-degree (no self-loop)
__device__ int   g_rowptr[MAX_N];
__device__ int   g_cursor[MAX_N];
__device__ int   g_uhist[MAX_N];     // user_idx counts
__device__ int   g_urowptr[MAX_N];
__device__ int   g_ucursor[MAX_N];
__device__ int   g_unodes[MAX_N];    // CSR payload for user_idx
__device__ int   g_bsums[2 * MAX_BLKS + 2];
__device__ __align__(8) int2 g_erec[MAX_E];  // {src, norm bits}

// ---- tf32 helpers ---------------------------------------------------------
__device__ __forceinline__ unsigned int f2tf32(float f) {
    unsigned int u;
    asm("cvt.rna.tf32.f32 %0, %1;" : "=r"(u) : "f"(f));
    return u;
}
__device__ __forceinline__ void mma_tf32(float* d, const unsigned int* a,
                                         const unsigned int* b) {
    asm("mma.sync.aligned.m16n8k8.row.col.f32.tf32.tf32.f32 "
        "{%0,%1,%2,%3}, {%4,%5,%6,%7}, {%8,%9}, {%0,%1,%2,%3};"
        : "+f"(d[0]), "+f"(d[1]), "+f"(d[2]), "+f"(d[3])
        : "r"(a[0]), "r"(a[1]), "r"(a[2]), "r"(a[3]), "r"(b[0]), "r"(b[1]));
}

// ---------------------------------------------------------------------------
__global__ void k_zero_graph(int N) {
    int i = blockIdx.x * blockDim.x + threadIdx.x;
    if (i < N) { g_hist[i] = 0; g_cursor[i] = 0; g_uhist[i] = 0; g_ucursor[i] = 0; }
}

__global__ void k_histboth(const int* __restrict__ dst, const int* __restrict__ uidx,
                           int E, int N) {
    int i = blockIdx.x * blockDim.x + threadIdx.x;
    if (i < E)          atomicAdd(&g_hist[dst[i]], 1);
    else if (i < E + N) atomicAdd(&g_uhist[uidx[i - E]], 1);
}

// fused hierarchical scan, both CSRs in one grid; dis folded into which==0 pass
__global__ void __launch_bounds__(SCAN_TILE) k_scan_local(int nblk, int N) {
    __shared__ int sh[SCAN_TILE];
    int which = (blockIdx.x >= nblk) ? 1 : 0;
    int blk = blockIdx.x - which * nblk;
    const int* in = which ? g_uhist : g_hist;
    int* outp     = which ? g_urowptr : g_rowptr;
    int tid = threadIdx.x;
    int i = blk * SCAN_TILE + tid;
    int v = (i < N) ? in[i] : 0;
    sh[tid] = v;
    __syncthreads();
    for (int off = 1; off < SCAN_TILE; off <<= 1) {
        int t = (tid >= off) ? sh[tid - off] : 0;
        __syncthreads();
        sh[tid] += t;
        __syncthreads();
    }
    if (i < N) {
        outp[i] = sh[tid] - v;
        if (!which) g_dis[i] = rsqrtf((float)(v + 1));   // deg+1 (self-loop)
    }
    if (tid == SCAN_TILE - 1) g_bsums[blockIdx.x] = sh[tid];
}

__global__ void k_scan_sums(int nblk) {
    int t = threadIdx.x;
    if (t < 2) {
        int acc = 0;
        for (int b = t * nblk; b < (t + 1) * nblk; ++b) {
            int v = g_bsums[b]; g_bsums[b] = acc; acc += v;
        }
    }
}

__global__ void __launch_bounds__(SCAN_TILE) k_scan_add(int nblk, int N) {
    int which = (blockIdx.x >= nblk) ? 1 : 0;
    int blk = blockIdx.x - which * nblk;
    int* outp = which ? g_urowptr : g_rowptr;
    int i = blk * SCAN_TILE + threadIdx.x;
    if (i < N) outp[i] += g_bsums[blockIdx.x];
}

__global__ void k_scatterboth(const int* __restrict__ src, const int* __restrict__ dst,
                              const int* __restrict__ uidx, int E, int N) {
    int i = blockIdx.x * blockDim.x + threadIdx.x;
    if (i < E) {
        int s = src[i];
        int d = dst[i];
        int pos = g_rowptr[d] + atomicAdd(&g_cursor[d], 1);
        g_erec[pos] = make_int2(s, __float_as_int(g_dis[s] * g_dis[d]));
    } else if (i < E + N) {
        int n = i - E;
        int u = uidx[n];
        int pos = g_urowptr[u] + atomicAdd(&g_ucursor[u], 1);
        g_unodes[pos] = n;
    }
}

// ---------------------------------------------------------------------------
// Gather aggregation: warp per dst node, lane owns cols {2*lane, 2*lane+1}
// (float2). Edge records read cooperatively (32/warp, coalesced) and
// shuffle-broadcast. Reads g_bufA, writes g_bufB.
// ---------------------------------------------------------------------------
__global__ void __launch_bounds__(256) k_aggr(const float* __restrict__ bias,
                                              int N, int do_relu) {
    int d = (blockIdx.x * blockDim.x + threadIdx.x) >> 5;
    int lane = threadIdx.x & 31;
    if (d >= N) return;

    const float2* __restrict__ h2 = (const float2*)g_bufA;

    float sd = g_dis[d];
    float w = sd * sd;
    float2 hv = h2[(size_t)d * 32 + lane];
    float ax = w * hv.x;
    float ay = w * hv.y;

    int beg = g_rowptr[d];
    int deg = g_hist[d];
    for (int base = 0; base < deg; base += 32) {
        int n = deg - base; if (n > 32) n = 32;
        int2 r = g_erec[beg + base + ((lane < n) ? lane : 0)];
#pragma unroll 4
        for (int j = 0; j < n; ++j) {
            int   s    = __shfl_sync(0xffffffffu, r.x, j);
            float norm = __int_as_float(__shfl_sync(0xffffffffu, r.y, j));
            float2 hs = h2[(size_t)s * 32 + lane];
            ax = fmaf(norm, hs.x, ax);
            ay = fmaf(norm, hs.y, ay);
        }
    }

    float2 bb = ((const float2*)bias)[lane];
    ax += bb.x; ay += bb.y;
    if (do_relu) { ax = fmaxf(ax, 0.f); ay = fmaxf(ay, 0.f); }
    ((float2*)g_bufB)[(size_t)d * 32 + lane] = make_float2(ax, ay);
}

// ---------------------------------------------------------------------------
// scatter-mean as gather: warp per user u; float2 lanes; plain store to d_out.
// ---------------------------------------------------------------------------
__global__ void __launch_bounds__(256) k_umean(float* __restrict__ out, int N) {
    int u = (blockIdx.x * blockDim.x + threadIdx.x) >> 5;
    int lane = threadIdx.x & 31;
    if (u >= N) return;
    const float2* __restrict__ h2 = (const float2*)g_bufB;
    int cnt = g_uhist[u];
    float ax = 0.f, ay = 0.f;
    int beg = g_urowptr[u];
    for (int base = 0; base < cnt; base += 32) {
        int n = cnt - base; if (n > 32) n = 32;
        int node_l = g_unodes[beg + base + ((lane < n) ? lane : 0)];
#pragma unroll 4
        for (int j = 0; j < n; ++j) {
            int node = __shfl_sync(0xffffffffu, node_l, j);
            float2 hs = h2[(size_t)node * 32 + lane];
            ax += hs.x; ay += hs.y;
        }
    }
    float inv = (cnt > 0) ? 1.0f / (float)cnt : 0.f;
    ((float2*)out)[(size_t)u * 32 + lane] = make_float2(ax * inv, ay * inv);
}

// ---------------------------------------------------------------------------
// tf32 tensor-core GEMM: g_bufA[N][64] = A[N][K] @ W[K][64].
// Block 128x64 (256 thr, 8 warps in 4x2), warp tile 32x32 via
// mma.sync.m16n8k8.tf32 (2 m-frag x 4 n-frag). Inputs truncated to tf32 at
// smem staging (cvt.rna); accumulation fp32. A chunked by 32 k, W staged once.
// ---------------------------------------------------------------------------
template <int K>
__global__ void __launch_bounds__(256) gemm_kernel(const float* __restrict__ Ax,
                                                   const float* __restrict__ W,
                                                   int in_sel, int N) {
    const float* __restrict__ A = in_sel ? (const float*)g_bufB : Ax;
    __shared__ unsigned int Ws[K][72];   // tf32 bits; stride 72: frag loads conflict-free
    __shared__ unsigned int xs[128][36]; // tf32 bits; stride 36: frag loads conflict-free

    int tid = threadIdx.x;
    int lane = tid & 31;
    int warp = tid >> 5;
    int warpRow = warp >> 1;            // 0..3 -> 32-row strip
    int warpCol = warp & 1;             // 0..1 -> 32-col strip
    int g = lane >> 2;                  // 0..7
    int tig = lane & 3;                 // 0..3
    int row0 = blockIdx.x * 128;

    // stage W (tf32) once
    for (int i = tid; i < K * 64; i += 256)
        Ws[i >> 6][i & 63] = f2tf32(W[i]);

    float acc[2][4][4];
#pragma unroll
    for (int mi = 0; mi < 2; ++mi)
#pragma unroll
        for (int ni = 0; ni < 4; ++ni)
#pragma unroll
            for (int q = 0; q < 4; ++q) acc[mi][ni][q] = 0.f;

    for (int k0 = 0; k0 < K; k0 += 32) {
        __syncthreads();
        // stage A chunk (tf32): 128 rows x 32 k
#pragma unroll
        for (int it = 0; it < 4; ++it) {
            int r  = (tid >> 3) + it * 32;   // 0..127
            int kk = (tid & 7) * 4;          // 0..28
            int row = row0 + r;
            float4 v = make_float4(0.f, 0.f, 0.f, 0.f);
            if (row < N)
                v = *(const float4*)(A + (size_t)row * K + k0 + kk);
            *(uint4*)&xs[r][kk] = make_uint4(f2tf32(v.x), f2tf32(v.y),
                                             f2tf32(v.z), f2tf32(v.w));
        }
        __syncthreads();
#pragma unroll
        for (int k8 = 0; k8 < 4; ++k8) {
            int kl = k8 * 8;                 // k within chunk (xs)
            int kg = k0 + kl;                // k within W (Ws)
            unsigned int a[2][4];
#pragma unroll
            for (int mi = 0; mi < 2; ++mi) {
                int r = warpRow * 32 + mi * 16 + g;
                a[mi][0] = xs[r][kl + tig];
                a[mi][1] = xs[r + 8][kl + tig];
                a[mi][2] = xs[r][kl + tig + 4];
                a[mi][3] = xs[r + 8][kl + tig + 4];
            }
            unsigned int b[4][2];
#pragma unroll
            for (int ni = 0; ni < 4; ++ni) {
                int j = warpCol * 32 + ni * 8 + g;
                b[ni][0] = Ws[kg + tig][j];
                b[ni][1] = Ws[kg + tig + 4][j];
            }
#pragma unroll
            for (int mi = 0; mi < 2; ++mi)
#pragma unroll
                for (int ni = 0; ni < 4; ++ni)
                    mma_tf32(acc[mi][ni], a[mi], b[ni]);
        }
    }

    // epilogue: c0,c1 -> (row g, cols 2tig,2tig+1); c2,c3 -> row g+8
#pragma unroll
    for (int mi = 0; mi < 2; ++mi) {
#pragma unroll
        for (int ni = 0; ni < 4; ++ni) {
            int col = warpCol * 32 + ni * 8 + tig * 2;
            int rA = row0 + warpRow * 32 + mi * 16 + g;
            int rB = rA + 8;
            if (rA < N)
                *(float2*)(&g_bufA[(size_t)rA * 64 + col]) =
                    make_float2(acc[mi][ni][0], acc[mi][ni][1]);
            if (rB < N)
                *(float2*)(&g_bufA[(size_t)rB * 64 + col]) =
                    make_float2(acc[mi][ni][2], acc[mi][ni][3]);
        }
    }
}

// ---------------------------------------------------------------------------
static inline int cdiv(int a, int b) { return (a + b - 1) / b; }

extern "C" void kernel_launch(void* const* d_in, const int* in_sizes, int n_in,
                              void* d_out, int out_size) {
    const float* x    = (const float*)d_in[0];
    const int*   ei   = (const int*)d_in[1];      // int32 per harness dtype contract
    const int*   uidx = (const int*)d_in[2];
    const float* W1   = (const float*)d_in[3];
    const float* b1   = (const float*)d_in[4];
    const float* W2   = (const float*)d_in[5];
    const float* b2   = (const float*)d_in[6];
    float* out = (float*)d_out;

    const int N = in_sizes[2];
    const int E = in_sizes[1] / 2;
    const int* src = ei;
    const int* dst = ei + E;

    const int TB = 256;
    const int nblk = cdiv(N, SCAN_TILE);

    // 1-3: graph prep
    k_zero_graph<<<cdiv(N, TB), TB>>>(N);
    k_histboth<<<cdiv(E + N, TB), TB>>>(dst, uidx, E, N);
    k_scan_local<<<2 * nblk, SCAN_TILE>>>(nblk, N);
    // 4: gemm1 (x -> bufA) — kept at slot 4 for the ncu window
    gemm_kernel<128><<<cdiv(N, 128), 256>>>(x, W1, 0, N);
    // 5-7: finish CSRs
    k_scan_sums<<<1, 32>>>(nblk);
    k_scan_add<<<2 * nblk, SCAN_TILE>>>(nblk, N);
    k_scatterboth<<<cdiv(E + N, TB), TB>>>(src, dst, uidx, E, N);
    // 8: layer-1 aggregate (bufA -> bufB, +b1, relu)
    k_aggr<<<cdiv(N * 32, TB), TB>>>(b1, N, 1);
    // 9-10: layer 2
    gemm_kernel<64><<<cdiv(N, 128), 256>>>(x, W2, 1, N);   // bufB -> bufA
    k_aggr<<<cdiv(N * 32, TB), TB>>>(b2, N, 0);            // bufA -> bufB
    // 11: scatter-mean (bufB -> out)
    k_umean<<<cdiv(N * 32, TB), TB>>>(out, N);
}